// round 1
// baseline (speedup 1.0000x reference)
#include <cuda_runtime.h>
#include <cstdint>

#define HPF 32
#define NBLK 20
#define HID 640
#define BATCH 128
#define SEQ 512
#define INSZ 16
#define BPW 4                       // batches per warp
#define NGROUP (BATCH / BPW)        // 32
#define NUNITS (NBLK * NGROUP)      // 640 warp-units
#define NCTA 152
#define WPC 5                       // warps per CTA
#define SMEM_FLOATS_PER_WARP (4 * HPF * HPF)   // 4096 floats = 16KB

__device__ __forceinline__ float sigm(float x) {
    return __fdividef(1.0f, 1.0f + __expf(-x));
}
__device__ __forceinline__ float tanhfast(float x) {
    return 2.0f * __fdividef(1.0f, 1.0f + __expf(-2.0f * x)) - 1.0f;
}

__global__ __launch_bounds__(WPC * 32, 1)
void lstm_fused_kernel(const float* __restrict__ x,
                       const float* __restrict__ Ui, const float* __restrict__ Vi, const float* __restrict__ bi,
                       const float* __restrict__ Uf, const float* __restrict__ Vf, const float* __restrict__ bf,
                       const float* __restrict__ Uc, const float* __restrict__ Vc, const float* __restrict__ bc,
                       const float* __restrict__ Uo, const float* __restrict__ Vo, const float* __restrict__ bo,
                       float* __restrict__ out, long long out_size)
{
    extern __shared__ float smem[];
    const int w    = threadIdx.x >> 5;
    const int lane = threadIdx.x & 31;
    const int unit = w * NCTA + blockIdx.x;
    if (unit >= NUNITS) return;

    const int j   = unit % NBLK;        // hidden block index 0..19
    const int grp = unit / NBLK;        // batch group 0..31
    const int b0  = grp * BPW;

    float* vs = smem + w * SMEM_FLOATS_PER_WARP;   // layout: vs[(m*32+n)*4 + g]

    // ---- Load the 4 recurrent 32x32 blocks (mask = block diagonal) ----
    const float* Vg[4] = {Vi, Vf, Vc, Vo};
    const int vbase = (j * HPF) * HID + j * HPF;
    #pragma unroll
    for (int g = 0; g < 4; ++g) {
        const float* V = Vg[g];
        #pragma unroll 8
        for (int m = 0; m < HPF; ++m) {
            vs[(m * HPF + lane) * 4 + g] = V[vbase + m * HID + lane];
        }
    }
    __syncwarp();

    // ---- Effective input-projection vectors (masked U rows collapsed) ----
    // block j (j<16): xu = b + x_j * U[j,:]
    // block 0 adds:   x0 * U[16,:] + x1 * U[17,:]   -> fold U[16] into ua, U[17]->ub
    // block 2 adds:   x2 * U[18,:] + x3 * U[19,:]
    // blocks 16..19:  xu = b only
    const float* Ug[4] = {Ui, Uf, Uc, Uo};
    const float* bg[4] = {bi, bf, bc, bo};
    float ua[4], ub[4], bias[4];
    const int col = j * HPF + lane;
    #pragma unroll
    for (int g = 0; g < 4; ++g) {
        float a = 0.0f, bb = 0.0f;
        if (j < 16) a = Ug[g][j * HID + col];
        if (j == 0) { a += Ug[g][16 * HID + col]; bb = Ug[g][17 * HID + col]; }
        if (j == 2) { a += Ug[g][18 * HID + col]; bb = Ug[g][19 * HID + col]; }
        ua[g] = a; ub[g] = bb;
        bias[g] = bg[g][col];
    }
    const int fa = (j == 0) ? 0 : ((j == 2) ? 2 : ((j < 16) ? j : 0));
    const int fb = (j == 0) ? 1 : ((j == 2) ? 3 : 0);   // ub==0 when unused

    const float* xp[BPW];
    #pragma unroll
    for (int k = 0; k < BPW; ++k)
        xp[k] = x + (long long)(b0 + k) * SEQ * INSZ;

    float h[BPW], cst[BPW];
    #pragma unroll
    for (int k = 0; k < BPW; ++k) { h[k] = 0.0f; cst[k] = 0.0f; }

    const int outcol = j * HPF + lane;

    for (int t = 0; t < SEQ; ++t) {
        // input scalars (broadcast loads, L1-resident: x is only 4MB total)
        float xa[BPW], xb[BPW];
        #pragma unroll
        for (int k = 0; k < BPW; ++k) {
            xa[k] = __ldg(xp[k] + t * INSZ + fa);
            xb[k] = __ldg(xp[k] + t * INSZ + fb);
        }

        float acc[BPW][4];
        #pragma unroll
        for (int k = 0; k < BPW; ++k) {
            acc[k][0] = 0.0f; acc[k][1] = 0.0f; acc[k][2] = 0.0f; acc[k][3] = 0.0f;
        }

        // 4 independent 32x32 matvecs (one per gate), 4 batches at a time.
        #pragma unroll
        for (int m = 0; m < HPF; ++m) {
            float4 v = *reinterpret_cast<const float4*>(vs + (m * HPF + lane) * 4);
            #pragma unroll
            for (int k = 0; k < BPW; ++k) {
                float hm = __shfl_sync(0xffffffffu, h[k], m);
                acc[k][0] = fmaf(hm, v.x, acc[k][0]);
                acc[k][1] = fmaf(hm, v.y, acc[k][1]);
                acc[k][2] = fmaf(hm, v.z, acc[k][2]);
                acc[k][3] = fmaf(hm, v.w, acc[k][3]);
            }
        }

        #pragma unroll
        for (int k = 0; k < BPW; ++k) {
            float gi = acc[k][0] + bias[0] + xa[k] * ua[0] + xb[k] * ub[0];
            float gf = acc[k][1] + bias[1] + xa[k] * ua[1] + xb[k] * ub[1];
            float gg = acc[k][2] + bias[2] + xa[k] * ua[2] + xb[k] * ub[2];
            float go = acc[k][3] + bias[3] + xa[k] * ua[3] + xb[k] * ub[3];

            float it = sigm(gi);
            float ft = sigm(gf);
            float gt = tanhfast(gg);
            float ot = sigm(go);

            cst[k] = ft * cst[k] + it * gt;
            h[k]   = ot * tanhfast(cst[k]);

            out[((long long)(b0 + k) * SEQ + t) * HID + outcol] = h[k];
        }
    }

    // final (h_t, c_t) appended after hidden_seq if the output buffer includes them
    const long long hs = (long long)BATCH * SEQ * HID;
    if (out_size >= hs + 2LL * BATCH * HID) {
        #pragma unroll
        for (int k = 0; k < BPW; ++k) {
            out[hs + (long long)(b0 + k) * HID + outcol] = h[k];
            out[hs + (long long)BATCH * HID + (long long)(b0 + k) * HID + outcol] = cst[k];
        }
    }
}

extern "C" void kernel_launch(void* const* d_in, const int* in_sizes, int n_in,
                              void* d_out, int out_size)
{
    const float* x  = (const float*)d_in[0];
    const float* Ui = (const float*)d_in[1];
    const float* Vi = (const float*)d_in[2];
    const float* bi = (const float*)d_in[3];
    const float* Uf = (const float*)d_in[4];
    const float* Vf = (const float*)d_in[5];
    const float* bf = (const float*)d_in[6];
    const float* Uc = (const float*)d_in[7];
    const float* Vc = (const float*)d_in[8];
    const float* bc = (const float*)d_in[9];
    const float* Uo = (const float*)d_in[10];
    const float* Vo = (const float*)d_in[11];
    const float* bo = (const float*)d_in[12];
    float* out = (float*)d_out;

    const int smem_bytes = WPC * SMEM_FLOATS_PER_WARP * (int)sizeof(float);  // 80KB
    cudaFuncSetAttribute(lstm_fused_kernel,
                         cudaFuncAttributeMaxDynamicSharedMemorySize, smem_bytes);

    lstm_fused_kernel<<<NCTA, WPC * 32, smem_bytes>>>(
        x, Ui, Vi, bi, Uf, Vf, bf, Uc, Vc, bc, Uo, Vo, bo,
        out, (long long)out_size);
}

// round 2
// speedup vs baseline: 1.0628x; 1.0628x over previous
#include <cuda_runtime.h>

#define HPF 32
#define NBLK 20
#define HID 640
#define BATCHN 128
#define SEQ 512
#define INSZ 16
#define BPW 4                      // batches per warp
#define WPC 4                      // warps per CTA (one CTA = one j-block, 16 batches)
#define TPB (WPC * 32)
#define NCTA 160                   // NBLK * (BATCHN / (BPW*WPC)) = 20 * 8

#define HSTRIDE 36                 // floats per (batch) row in h stage (16B-aligned stride)
#define HBUF (BPW * HSTRIDE)       // 144 floats per buffer per warp
#define HWARP (2 * HBUF)           // 288 floats per warp (double buffered)
#define SMEM_V (4 * HPF * HPF)     // 4096 floats (two 2048 regions: gates 01 / 23)
#define SMEM_FLOATS (SMEM_V + WPC * HWARP)   // 4096 + 1152 = 5248 floats (~21KB)

// ---- packed fp32x2 helpers (sm_103a dual-issue fp32) ----
__device__ __forceinline__ unsigned long long pk2(float a, float b) {
    unsigned long long r;
    asm("mov.b64 %0, {%1, %2};" : "=l"(r) : "f"(a), "f"(b));
    return r;
}
__device__ __forceinline__ float2 upk2(unsigned long long v) {
    float2 f;
    asm("mov.b64 {%0, %1}, %2;" : "=f"(f.x), "=f"(f.y) : "l"(v));
    return f;
}
__device__ __forceinline__ void fma2(unsigned long long& d,
                                     unsigned long long a, unsigned long long b) {
    asm("fma.rn.f32x2 %0, %1, %2, %0;" : "+l"(d) : "l"(a), "l"(b));
}

__device__ __forceinline__ float sigm(float x) {
    return __fdividef(1.0f, 1.0f + __expf(-x));
}
__device__ __forceinline__ float tanhfast(float x) {
    return 2.0f * __fdividef(1.0f, 1.0f + __expf(-2.0f * x)) - 1.0f;
}

__global__ __launch_bounds__(TPB, 1)
void lstm_fused_kernel(const float* __restrict__ x,
                       const float* __restrict__ Ui, const float* __restrict__ Vi, const float* __restrict__ bi,
                       const float* __restrict__ Uf, const float* __restrict__ Vf, const float* __restrict__ bf,
                       const float* __restrict__ Uc, const float* __restrict__ Vc, const float* __restrict__ bc,
                       const float* __restrict__ Uo, const float* __restrict__ Vo, const float* __restrict__ bo,
                       float* __restrict__ out, long long out_size)
{
    __shared__ float smem[SMEM_FLOATS];
    const int w    = threadIdx.x >> 5;
    const int lane = threadIdx.x & 31;
    const int j    = blockIdx.x % NBLK;       // hidden block 0..19
    const int grp  = blockIdx.x / NBLK;       // 0..7 (16-batch group)
    const int b0   = grp * 16 + w * BPW;      // first batch of this warp

    const float* Vg[4] = {Vi, Vf, Vc, Vo};
    const float* Ug[4] = {Ui, Uf, Uc, Uo};
    const float* bg[4] = {bi, bf, bc, bo};

    // ---- cooperative V load into packed conflict-free layout ----
    // region A (offset 0):    gates 0,1   region B (offset 2048): gates 2,3
    // layout: reg[((m/2)*32 + n)*4 + (g&1)*2 + (m&1)]
    // -> per (m-pair mp, lane n): 4 contiguous floats (16B) per region => LDS.128
    //    with 16B lane stride = conflict-free.
    for (int idx = threadIdx.x; idx < 4 * HPF * HPF; idx += TPB) {
        const int n = idx & 31;
        const int m = (idx >> 5) & 31;
        const int g = idx >> 10;
        const float v = Vg[g][(j * HPF + m) * HID + j * HPF + n];
        const int region = (g < 2) ? 0 : 2048;
        smem[region + (((m >> 1) * 32 + n) * 4) + (g & 1) * 2 + (m & 1)] = v;
    }

    // ---- zero h staging buffers ----
    float* hs = smem + SMEM_V + w * HWARP;
    for (int i = lane; i < HWARP; i += 32) hs[i] = 0.0f;
    __syncthreads();

    // ---- folded input projection (masked U rows) ----
    float ua[4], ub[4], bias[4];
    const int col = j * HPF + lane;
    #pragma unroll
    for (int g = 0; g < 4; ++g) {
        float a = 0.0f, bb = 0.0f;
        if (j < 16) a = Ug[g][j * HID + col];
        if (j == 0) { a += Ug[g][16 * HID + col]; bb = Ug[g][17 * HID + col]; }
        if (j == 2) { a += Ug[g][18 * HID + col]; bb = Ug[g][19 * HID + col]; }
        ua[g] = a; ub[g] = bb;
        bias[g] = bg[g][col];
    }
    const int fa = (j == 0) ? 0 : ((j == 2) ? 2 : ((j < 16) ? j : 0));
    const int fb = (j == 0) ? 1 : ((j == 2) ? 3 : 0);   // ub==0 when unused

    const float* xp[BPW];
    #pragma unroll
    for (int k = 0; k < BPW; ++k)
        xp[k] = x + (long long)(b0 + k) * SEQ * INSZ;

    float h[BPW], cst[BPW];
    #pragma unroll
    for (int k = 0; k < BPW; ++k) { h[k] = 0.0f; cst[k] = 0.0f; }

    const int outcol = j * HPF + lane;

    for (int t = 0; t < SEQ; ++t) {
        const float* hr = hs + ((t & 1) ? HBUF : 0);     // read buffer
        float*       hw = hs + ((t & 1) ? 0 : HBUF);     // write buffer

        // x gather (broadcast loads; x slice stays L1/L2 resident)
        float xa[BPW], xb[BPW];
        #pragma unroll
        for (int k = 0; k < BPW; ++k) {
            xa[k] = __ldg(xp[k] + t * INSZ + fa);
            xb[k] = __ldg(xp[k] + t * INSZ + fb);
        }

        // acc[k][g] packed: lo = even-m partial, hi = odd-m partial.
        // fold bias + input projection into lo half at init.
        unsigned long long acc[BPW][4];
        #pragma unroll
        for (int k = 0; k < BPW; ++k) {
            #pragma unroll
            for (int g = 0; g < 4; ++g)
                acc[k][g] = pk2(fmaf(xb[k], ub[g], fmaf(xa[k], ua[g], bias[g])), 0.0f);
        }

        // 4 gate matvecs, packed over m-pairs. Per q: m in [4q, 4q+4).
        #pragma unroll
        for (int q = 0; q < 8; ++q) {
            const ulonglong2 vA0 = *reinterpret_cast<const ulonglong2*>(smem + ((2 * q) * 32 + lane) * 4);
            const ulonglong2 vB0 = *reinterpret_cast<const ulonglong2*>(smem + 2048 + ((2 * q) * 32 + lane) * 4);
            const ulonglong2 vA1 = *reinterpret_cast<const ulonglong2*>(smem + ((2 * q + 1) * 32 + lane) * 4);
            const ulonglong2 vB1 = *reinterpret_cast<const ulonglong2*>(smem + 2048 + ((2 * q + 1) * 32 + lane) * 4);
            #pragma unroll
            for (int k = 0; k < BPW; ++k) {
                const ulonglong2 h01 = *reinterpret_cast<const ulonglong2*>(hr + k * HSTRIDE + 4 * q);
                fma2(acc[k][0], h01.x, vA0.x);
                fma2(acc[k][1], h01.x, vA0.y);
                fma2(acc[k][2], h01.x, vB0.x);
                fma2(acc[k][3], h01.x, vB0.y);
                fma2(acc[k][0], h01.y, vA1.x);
                fma2(acc[k][1], h01.y, vA1.y);
                fma2(acc[k][2], h01.y, vB1.x);
                fma2(acc[k][3], h01.y, vB1.y);
            }
        }

        #pragma unroll
        for (int k = 0; k < BPW; ++k) {
            const float2 p0 = upk2(acc[k][0]);
            const float2 p1 = upk2(acc[k][1]);
            const float2 p2 = upk2(acc[k][2]);
            const float2 p3 = upk2(acc[k][3]);
            const float gi = p0.x + p0.y;
            const float gf = p1.x + p1.y;
            const float gg = p2.x + p2.y;
            const float go = p3.x + p3.y;

            const float it = sigm(gi);
            const float ft = sigm(gf);
            const float gt = tanhfast(gg);
            const float ot = sigm(go);

            cst[k] = ft * cst[k] + it * gt;
            h[k]   = ot * tanhfast(cst[k]);

            out[((long long)(b0 + k) * SEQ + t) * HID + outcol] = h[k];
            hw[k * HSTRIDE + lane] = h[k];
        }
        __syncwarp();
    }

    // final (h_t, c_t) appended after hidden_seq when present in output buffer
    const long long hsz = (long long)BATCHN * SEQ * HID;
    if (out_size >= hsz + 2LL * BATCHN * HID) {
        #pragma unroll
        for (int k = 0; k < BPW; ++k) {
            out[hsz + (long long)(b0 + k) * HID + outcol] = h[k];
            out[hsz + (long long)BATCHN * HID + (long long)(b0 + k) * HID + outcol] = cst[k];
        }
    }
}

extern "C" void kernel_launch(void* const* d_in, const int* in_sizes, int n_in,
                              void* d_out, int out_size)
{
    const float* x  = (const float*)d_in[0];
    const float* Ui = (const float*)d_in[1];
    const float* Vi = (const float*)d_in[2];
    const float* bi = (const float*)d_in[3];
    const float* Uf = (const float*)d_in[4];
    const float* Vf = (const float*)d_in[5];
    const float* bf = (const float*)d_in[6];
    const float* Uc = (const float*)d_in[7];
    const float* Vc = (const float*)d_in[8];
    const float* bc = (const float*)d_in[9];
    const float* Uo = (const float*)d_in[10];
    const float* Vo = (const float*)d_in[11];
    const float* bo = (const float*)d_in[12];
    float* out = (float*)d_out;

    lstm_fused_kernel<<<NCTA, TPB>>>(
        x, Ui, Vi, bi, Uf, Vf, bf, Uc, Vc, bc, Uo, Vo, bo,
        out, (long long)out_size);
}

// round 3
// speedup vs baseline: 1.2346x; 1.1616x over previous
#include <cuda_runtime.h>

#define HPF 32
#define NBLK 20
#define HID 640
#define BATCHN 128
#define SEQ 512
#define INSZ 16
#define WPC 8
#define TPB (WPC * 32)
#define NCTA 148
#define WPJ 59                      // warps assigned per j-block (59*20=1180 active warps)

// ---- packed fp32x2 helpers (sm_103a dual fp32) ----
__device__ __forceinline__ unsigned long long pk2(float a, float b) {
    unsigned long long r;
    asm("mov.b64 %0, {%1, %2};" : "=l"(r) : "f"(a), "f"(b));
    return r;
}
__device__ __forceinline__ float2 upk2(unsigned long long v) {
    float2 f;
    asm("mov.b64 {%0, %1}, %2;" : "=f"(f.x), "=f"(f.y) : "l"(v));
    return f;
}
__device__ __forceinline__ void fma2(unsigned long long& d,
                                     unsigned long long a, unsigned long long b) {
    asm("fma.rn.f32x2 %0, %1, %2, %0;" : "+l"(d) : "l"(a), "l"(b));
}

__device__ __forceinline__ float sigm(float x) {
    return __fdividef(1.0f, 1.0f + __expf(-x));
}
__device__ __forceinline__ float tanhfast(float x) {
    return 2.0f * __fdividef(1.0f, 1.0f + __expf(-2.0f * x)) - 1.0f;
}

template<int NB>
__device__ __forceinline__ void lstm_unit(
    const int j, const int b0, const int lane, float* __restrict__ hs,
    const float* __restrict__ x,
    const float* __restrict__ V0, const float* __restrict__ V1,
    const float* __restrict__ V2, const float* __restrict__ V3,
    const float* __restrict__ U0, const float* __restrict__ U1,
    const float* __restrict__ U2, const float* __restrict__ U3,
    const float* __restrict__ B0, const float* __restrict__ B1,
    const float* __restrict__ B2, const float* __restrict__ B3,
    float* __restrict__ out, const long long out_size)
{
    const int col = j * HPF + lane;

    // ---- V blocks -> registers, packed over m-pairs: vr[g][q] = (V[2q][n], V[2q+1][n]) ----
    unsigned long long vr[4][16];
    const float* Vg[4] = {V0, V1, V2, V3};
    #pragma unroll
    for (int g = 0; g < 4; ++g) {
        #pragma unroll
        for (int q = 0; q < 16; ++q) {
            const float v0 = __ldg(&Vg[g][(j * HPF + 2 * q)     * HID + col]);
            const float v1 = __ldg(&Vg[g][(j * HPF + 2 * q + 1) * HID + col]);
            vr[g][q] = pk2(v0, v1);
        }
    }

    // ---- folded input projection (masked U rows collapsed) ----
    const float* Ug[4] = {U0, U1, U2, U3};
    const float* Bg[4] = {B0, B1, B2, B3};
    float ua[4], ub[4], bias[4];
    #pragma unroll
    for (int g = 0; g < 4; ++g) {
        float a = 0.0f, bb = 0.0f;
        if (j < 16) a = __ldg(&Ug[g][j * HID + col]);
        if (j == 0) { a += __ldg(&Ug[g][16 * HID + col]); bb = __ldg(&Ug[g][17 * HID + col]); }
        if (j == 2) { a += __ldg(&Ug[g][18 * HID + col]); bb = __ldg(&Ug[g][19 * HID + col]); }
        ua[g] = a; ub[g] = bb;
        bias[g] = __ldg(&Bg[g][col]);
    }
    const int fa = (j == 0) ? 0 : ((j == 2) ? 2 : ((j < 16) ? j : 0));
    const int fb = (j == 0) ? 1 : ((j == 2) ? 3 : 0);   // ub==0 when unused

    const float* xp[NB];
    float h[NB], c[NB];
    #pragma unroll
    for (int k = 0; k < NB; ++k) {
        xp[k] = x + (long long)(b0 + k) * SEQ * INSZ;
        h[k] = 0.0f; c[k] = 0.0f;
        hs[k * HPF + lane] = 0.0f;
    }
    __syncwarp();

    for (int t = 0; t < SEQ; ++t) {
        float xa[NB], xb[NB];
        #pragma unroll
        for (int k = 0; k < NB; ++k) {
            xa[k] = __ldg(xp[k] + t * INSZ + fa);
            xb[k] = __ldg(xp[k] + t * INSZ + fb);
        }

        // acc[k][g]: lo = even-m partial (+ bias + input proj), hi = odd-m partial
        unsigned long long acc[NB][4];
        #pragma unroll
        for (int k = 0; k < NB; ++k)
            #pragma unroll
            for (int g = 0; g < 4; ++g)
                acc[k][g] = pk2(fmaf(xb[k], ub[g], fmaf(xa[k], ua[g], bias[g])), 0.0f);

        // register-resident matvec; h pairs via broadcast LDS.64
        #pragma unroll
        for (int q = 0; q < 16; ++q) {
            unsigned long long hp[NB];
            #pragma unroll
            for (int k = 0; k < NB; ++k)
                hp[k] = *reinterpret_cast<const unsigned long long*>(hs + k * HPF + 2 * q);
            #pragma unroll
            for (int k = 0; k < NB; ++k) {
                fma2(acc[k][0], hp[k], vr[0][q]);
                fma2(acc[k][1], hp[k], vr[1][q]);
                fma2(acc[k][2], hp[k], vr[2][q]);
                fma2(acc[k][3], hp[k], vr[3][q]);
            }
        }
        __syncwarp();   // all h reads complete before overwrite

        #pragma unroll
        for (int k = 0; k < NB; ++k) {
            const float2 p0 = upk2(acc[k][0]);
            const float2 p1 = upk2(acc[k][1]);
            const float2 p2 = upk2(acc[k][2]);
            const float2 p3 = upk2(acc[k][3]);
            const float it = sigm(p0.x + p0.y);
            const float ft = sigm(p1.x + p1.y);
            const float gt = tanhfast(p2.x + p2.y);
            const float ot = sigm(p3.x + p3.y);

            c[k] = ft * c[k] + it * gt;
            h[k] = ot * tanhfast(c[k]);

            out[((long long)(b0 + k) * SEQ + t) * HID + col] = h[k];
            hs[k * HPF + lane] = h[k];
        }
        __syncwarp();   // writes visible before next step's reads
    }

    const long long hsz = (long long)BATCHN * SEQ * HID;
    if (out_size >= hsz + 2LL * BATCHN * HID) {
        #pragma unroll
        for (int k = 0; k < NB; ++k) {
            out[hsz + (long long)(b0 + k) * HID + col] = h[k];
            out[hsz + (long long)BATCHN * HID + (long long)(b0 + k) * HID + col] = c[k];
        }
    }
}

__global__ __launch_bounds__(TPB, 1)
void lstm_fused_kernel(const float* __restrict__ x,
                       const float* __restrict__ Ui, const float* __restrict__ Vi, const float* __restrict__ bi,
                       const float* __restrict__ Uf, const float* __restrict__ Vf, const float* __restrict__ bf,
                       const float* __restrict__ Uc, const float* __restrict__ Vc, const float* __restrict__ bc,
                       const float* __restrict__ Uo, const float* __restrict__ Vo, const float* __restrict__ bo,
                       float* __restrict__ out, long long out_size)
{
    __shared__ float hstage[WPC][3 * HPF];
    const int w    = threadIdx.x >> 5;
    const int lane = threadIdx.x & 31;
    const int gid  = blockIdx.x * WPC + w;

    const int j   = gid % NBLK;
    const int idx = gid / NBLK;
    if (idx >= WPJ) return;                    // 4 spare warps idle

    // scatter the 3-batch warps across SMs/SMSPs: bijection idx -> sidx
    const int sidx = (idx * 7) % WPJ;

    if (sidx < 10) {
        // 10 warps x 3 batches = batches [0,30)
        lstm_unit<3>(j, sidx * 3, lane, hstage[w], x,
                     Vi, Vf, Vc, Vo, Ui, Uf, Uc, Uo, bi, bf, bc, bo,
                     out, out_size);
    } else {
        // 49 warps x 2 batches = batches [30,128)
        lstm_unit<2>(j, 30 + (sidx - 10) * 2, lane, hstage[w], x,
                     Vi, Vf, Vc, Vo, Ui, Uf, Uc, Uo, bi, bf, bc, bo,
                     out, out_size);
    }
}

extern "C" void kernel_launch(void* const* d_in, const int* in_sizes, int n_in,
                              void* d_out, int out_size)
{
    const float* x  = (const float*)d_in[0];
    const float* Ui = (const float*)d_in[1];
    const float* Vi = (const float*)d_in[2];
    const float* bi = (const float*)d_in[3];
    const float* Uf = (const float*)d_in[4];
    const float* Vf = (const float*)d_in[5];
    const float* bf = (const float*)d_in[6];
    const float* Uc = (const float*)d_in[7];
    const float* Vc = (const float*)d_in[8];
    const float* bc = (const float*)d_in[9];
    const float* Uo = (const float*)d_in[10];
    const float* Vo = (const float*)d_in[11];
    const float* bo = (const float*)d_in[12];
    float* out = (float*)d_out;

    lstm_fused_kernel<<<NCTA, TPB>>>(
        x, Ui, Vi, bi, Uf, Vf, bf, Uc, Vc, bc, Uo, Vo, bo,
        out, (long long)out_size);
}